// round 12
// baseline (speedup 1.0000x reference)
#include <cuda_runtime.h>
#include <cuda_bf16.h>
#include <cstdint>

#define BB 64
#define TT 256
#define CC 384
#define HH 6
#define DD 64
#define BT (BB*TT)

// Scratch (device globals: allocation-free per harness rules)
__device__ float g_Q[BB*HH*TT*DD];   // [b][h][t][d]
__device__ float g_K[BB*HH*TT*DD];
__device__ float g_V[BB*HH*TT*DD];

// bf16 hi/lo split operands
__device__ __nv_bfloat16 g_Xh[BT*CC],  g_Xl[BT*CC];       // x rows [r][c]
__device__ __nv_bfloat16 g_Wth[3*CC*CC], g_Wtl[3*CC*CC];  // W^T [p][n=h*64+d][k]
__device__ __nv_bfloat16 g_Ah[BT*CC],  g_Al[BT*CC];       // attn out rows [r][c]
__device__ __nv_bfloat16 g_Wph[CC*CC], g_Wpl[CC*CC];      // Wp^T [n][k]

// ---------------------------------------------------------------------------
__device__ __forceinline__ void mma16816(float* c, const uint32_t* a, uint32_t b0, uint32_t b1) {
    asm volatile("mma.sync.aligned.m16n8k16.row.col.f32.bf16.bf16.f32 "
                 "{%0,%1,%2,%3}, {%4,%5,%6,%7}, {%8,%9}, {%0,%1,%2,%3};"
                 : "+f"(c[0]), "+f"(c[1]), "+f"(c[2]), "+f"(c[3])
                 : "r"(a[0]), "r"(a[1]), "r"(a[2]), "r"(a[3]), "r"(b0), "r"(b1));
}
__device__ __forceinline__ uint32_t lds32(const __nv_bfloat16* p) {
    return *(const uint32_t*)p;
}
// split (a,b) fp32 pair into packed bf16x2 hi and lo
__device__ __forceinline__ void split_pair(float a, float b, uint32_t& h, uint32_t& l) {
    __nv_bfloat16 ah = __float2bfloat16(a), bh = __float2bfloat16(b);
    __nv_bfloat162 hv; hv.x = ah; hv.y = bh;
    h = *(uint32_t*)&hv;
    __nv_bfloat162 lv = __floats2bfloat162_rn(a - __bfloat162float(ah),
                                              b - __bfloat162float(bh));
    l = *(uint32_t*)&lv;
}

// ---------------------------------------------------------------------------
// Prep kernels: fp32 -> bf16 hi/lo splits (+ transposes for B operands)
// ---------------------------------------------------------------------------
__global__ __launch_bounds__(256) void conv_x(const float* __restrict__ x) {
    int i = blockIdx.x * 256 + threadIdx.x;
    float v = x[i];
    __nv_bfloat16 h = __float2bfloat16(v);
    g_Xh[i] = h;
    g_Xl[i] = __float2bfloat16(v - __bfloat162float(h));
}
__global__ __launch_bounds__(256) void conv_w(
    const float* __restrict__ Wq, const float* __restrict__ Wk, const float* __restrict__ Wv)
{
    int i = blockIdx.x * 256 + threadIdx.x;          // 3*384*384
    int p = i / (CC * CC);
    int rem = i - p * CC * CC;
    int n = rem / CC, k = rem - n * CC;
    int h = n >> 6, d = n & 63;
    const float* W = (p == 0 ? Wq : (p == 1 ? Wk : Wv));
    float v = W[(h * CC + k) * DD + d];
    __nv_bfloat16 hi = __float2bfloat16(v);
    g_Wth[i] = hi;
    g_Wtl[i] = __float2bfloat16(v - __bfloat162float(hi));
}
__global__ __launch_bounds__(256) void conv_wp(const float* __restrict__ Wp) {
    int i = blockIdx.x * 256 + threadIdx.x;          // 384*384
    int n = i / CC, k = i - n * CC;
    float v = Wp[k * CC + n];
    __nv_bfloat16 hi = __float2bfloat16(v);
    g_Wph[i] = hi;
    g_Wpl[i] = __float2bfloat16(v - __bfloat162float(hi));
}

// ---------------------------------------------------------------------------
// HMMA GEMM: C[M,64-tile] = A[M,384]*B^T[n,384], 3-pass hi/lo.
// ROUND 10 CHANGE: fragment-level software pipeline — prefetch ks+1's frag
// registers while issuing ks's MMAs (ptxas wouldn't at 80 regs; we force it
// with explicit double buffers + __launch_bounds__(256,2) for 128-reg cap).
// ---------------------------------------------------------------------------
#define ASTR 72
#define HS_AH 0
#define HS_AL (128*ASTR)
#define HS_BH (2*128*ASTR)
#define HS_BL (2*128*ASTR + 64*ASTR)
#define HS_TOT (2*128*ASTR + 2*64*ASTR)   // 27648 elems = 55296 B

#define LOAD_FRAGS(BUF, KS) do {                                               \
    const int kofs_ = (KS) * 16 + 2 * tig;                                     \
    _Pragma("unroll")                                                          \
    for (int mi_ = 0; mi_ < 2; ++mi_) {                                        \
        const __nv_bfloat16* pH = AsH + (wm + mi_ * 16 + grp) * ASTR + kofs_;  \
        const __nv_bfloat16* pL = AsL + (wm + mi_ * 16 + grp) * ASTR + kofs_;  \
        fah[BUF][mi_][0] = lds32(pH);                                          \
        fah[BUF][mi_][1] = lds32(pH + 8 * ASTR);                               \
        fah[BUF][mi_][2] = lds32(pH + 8);                                      \
        fah[BUF][mi_][3] = lds32(pH + 8 * ASTR + 8);                           \
        fal[BUF][mi_][0] = lds32(pL);                                          \
        fal[BUF][mi_][1] = lds32(pL + 8 * ASTR);                               \
        fal[BUF][mi_][2] = lds32(pL + 8);                                      \
        fal[BUF][mi_][3] = lds32(pL + 8 * ASTR + 8);                           \
    }                                                                          \
    _Pragma("unroll")                                                          \
    for (int nb_ = 0; nb_ < 2; ++nb_) {                                        \
        const __nv_bfloat16* pH = BsH + (wn + nb_ * 16 + grp) * ASTR + kofs_;  \
        const __nv_bfloat16* pL = BsL + (wn + nb_ * 16 + grp) * ASTR + kofs_;  \
        fbh[BUF][nb_][0] = lds32(pH);                                          \
        fbh[BUF][nb_][1] = lds32(pH + 8);                                      \
        fbh[BUF][nb_][2] = lds32(pH + 8 * ASTR);                               \
        fbh[BUF][nb_][3] = lds32(pH + 8 * ASTR + 8);                           \
        fbl[BUF][nb_][0] = lds32(pL);                                          \
        fbl[BUF][nb_][1] = lds32(pL + 8);                                      \
        fbl[BUF][nb_][2] = lds32(pL + 8 * ASTR);                               \
        fbl[BUF][nb_][3] = lds32(pL + 8 * ASTR + 8);                           \
    }                                                                          \
} while (0)

__global__ __launch_bounds__(256, 2) void hmma_gemm(
    int mode, const float* __restrict__ bias, float* __restrict__ outp)
{
    extern __shared__ __nv_bfloat16 hsm[];
    __nv_bfloat16* AsH = hsm + HS_AH;
    __nv_bfloat16* AsL = hsm + HS_AL;
    __nv_bfloat16* BsH = hsm + HS_BH;
    __nv_bfloat16* BsL = hsm + HS_BL;

    const int tid  = threadIdx.x;
    const int lane = tid & 31;
    const int wid  = tid >> 5;
    const int m0   = blockIdx.x * 128;

    int p = 0, h2;
    const __nv_bfloat16 *Ah, *Al, *Bh, *Bl;
    float* O;
    if (mode == 0) {
        p = blockIdx.y / 6; h2 = blockIdx.y % 6;
        Ah = g_Xh; Al = g_Xl;
        Bh = g_Wth + p * CC * CC + h2 * 64 * CC;
        Bl = g_Wtl + p * CC * CC + h2 * 64 * CC;
        O  = (p == 0 ? g_Q : (p == 1 ? g_K : g_V));
    } else {
        h2 = blockIdx.y;
        Ah = g_Ah; Al = g_Al;
        Bh = g_Wph + h2 * 64 * CC;
        Bl = g_Wpl + h2 * 64 * CC;
        O  = outp;
    }

    const int wm = (wid & 3) * 32;
    const int wn = (wid >> 2) * 32;
    const int grp = lane >> 2;
    const int tig = lane & 3;

    float c[2][4][4] = {};
    uint32_t fah[2][2][4], fal[2][2][4], fbh[2][2][4], fbl[2][2][4];

    for (int ch = 0; ch < 6; ++ch) {
        const int kb = ch * 64;
        #pragma unroll
        for (int j = 0; j < 4; ++j) {
            int i = tid + j * 256;
            int row = i >> 3, q8 = i & 7;
            int dst = row * ASTR + q8 * 8;
            int gi  = (m0 + row) * CC + kb + q8 * 8;
            *(uint4*)(AsH + dst) = *(const uint4*)(Ah + gi);
            *(uint4*)(AsL + dst) = *(const uint4*)(Al + gi);
        }
        #pragma unroll
        for (int j = 0; j < 2; ++j) {
            int i = tid + j * 256;
            int row = i >> 3, q8 = i & 7;
            int dst = row * ASTR + q8 * 8;
            int gi  = row * CC + kb + q8 * 8;
            *(uint4*)(BsH + dst) = *(const uint4*)(Bh + gi);
            *(uint4*)(BsL + dst) = *(const uint4*)(Bl + gi);
        }
        __syncthreads();

        LOAD_FRAGS(0, 0);
        #pragma unroll
        for (int ks = 0; ks < 4; ++ks) {
            const int cur = ks & 1;
            if (ks < 3) { LOAD_FRAGS(!cur, ks + 1); }   // prefetch next frags
            #pragma unroll
            for (int mi = 0; mi < 2; ++mi) {
                #pragma unroll
                for (int ni = 0; ni < 4; ++ni) {
                    uint32_t b0h = fbh[cur][ni >> 1][(ni & 1) * 2];
                    uint32_t b1h = fbh[cur][ni >> 1][(ni & 1) * 2 + 1];
                    uint32_t b0l = fbl[cur][ni >> 1][(ni & 1) * 2];
                    uint32_t b1l = fbl[cur][ni >> 1][(ni & 1) * 2 + 1];
                    mma16816(c[mi][ni], fah[cur][mi], b0h, b1h);
                    mma16816(c[mi][ni], fah[cur][mi], b0l, b1l);
                    mma16816(c[mi][ni], fal[cur][mi], b0h, b1h);
                }
            }
        }
        __syncthreads();
    }

    #pragma unroll
    for (int mi = 0; mi < 2; ++mi) {
        #pragma unroll
        for (int ni = 0; ni < 4; ++ni) {
            int row0 = m0 + wm + mi * 16 + grp;
            int col  = wn + ni * 8 + tig * 2;
            if (mode == 0) {
                int b0i = row0 >> 8, t0 = row0 & 255;
                int r1 = row0 + 8, b1i = r1 >> 8, t1 = r1 & 255;
                *(float2*)(O + ((b0i * HH + h2) * TT + t0) * DD + col) =
                    make_float2(c[mi][ni][0], c[mi][ni][1]);
                *(float2*)(O + ((b1i * HH + h2) * TT + t1) * DD + col) =
                    make_float2(c[mi][ni][2], c[mi][ni][3]);
            } else {
                int n = h2 * 64 + col;
                float2 bv = *(const float2*)(bias + n);
                *(float2*)(O + (size_t)row0 * CC + n) =
                    make_float2(c[mi][ni][0] + bv.x, c[mi][ni][1] + bv.y);
                *(float2*)(O + (size_t)(row0 + 8) * CC + n) =
                    make_float2(c[mi][ni][2] + bv.x, c[mi][ni][3] + bv.y);
            }
        }
    }
}

// ---------------------------------------------------------------------------
// Flash-style HMMA causal attention (validated round 9, unchanged).
// ---------------------------------------------------------------------------
#define QSTR 72
#define VSTR 264
#define AF_QH 0
#define AF_QL (256*QSTR)
#define AF_KH (2*256*QSTR)
#define AF_KL (3*256*QSTR)
#define AF_VH (4*256*QSTR)
#define AF_VL (4*256*QSTR + 64*VSTR)
#define AF_TOT (4*256*QSTR + 2*64*VSTR)   // 107520 elems = 215040 B

__global__ __launch_bounds__(256) void attn_flash()
{
    extern __shared__ __nv_bfloat16 asm_[];
    __nv_bfloat16* Qh = asm_ + AF_QH;
    __nv_bfloat16* Ql = asm_ + AF_QL;
    __nv_bfloat16* Kh = asm_ + AF_KH;
    __nv_bfloat16* Kl = asm_ + AF_KL;
    __nv_bfloat16* Vh = asm_ + AF_VH;
    __nv_bfloat16* Vl = asm_ + AF_VL;

    const int bh  = blockIdx.x;
    const int tid = threadIdx.x;
    const int lane = tid & 31;
    const int wid  = tid >> 5;
    const int grp  = lane >> 2;
    const int tig  = lane & 3;

    const float4* Qg = (const float4*)(g_Q + (size_t)bh * TT * DD);
    const float4* Kg = (const float4*)(g_K + (size_t)bh * TT * DD);
    const float4* Vg = (const float4*)(g_V + (size_t)bh * TT * DD);
    #pragma unroll
    for (int j = 0; j < 16; ++j) {
        int i4 = tid + j * 256;
        int row = i4 >> 4, c4 = (i4 & 15) * 4;
        float4 qv = Qg[i4];
        uint32_t h0, l0, h1, l1;
        split_pair(qv.x, qv.y, h0, l0);
        split_pair(qv.z, qv.w, h1, l1);
        *(uint32_t*)(Qh + row * QSTR + c4)     = h0;
        *(uint32_t*)(Qh + row * QSTR + c4 + 2) = h1;
        *(uint32_t*)(Ql + row * QSTR + c4)     = l0;
        *(uint32_t*)(Ql + row * QSTR + c4 + 2) = l1;
        float4 kv = Kg[i4];
        split_pair(kv.x, kv.y, h0, l0);
        split_pair(kv.z, kv.w, h1, l1);
        *(uint32_t*)(Kh + row * QSTR + c4)     = h0;
        *(uint32_t*)(Kh + row * QSTR + c4 + 2) = h1;
        *(uint32_t*)(Kl + row * QSTR + c4)     = l0;
        *(uint32_t*)(Kl + row * QSTR + c4 + 2) = l1;
    }
    #pragma unroll
    for (int j = 0; j < 16; ++j) {
        int i4 = tid + j * 256;
        int d4 = i4 >> 8, s = i4 & 255;
        float4 vv = Vg[s * 16 + d4];
        float e[4] = {vv.x, vv.y, vv.z, vv.w};
        #pragma unroll
        for (int q = 0; q < 4; ++q) {
            int d = d4 * 4 + q;
            __nv_bfloat16 hb = __float2bfloat16(e[q]);
            Vh[d * VSTR + s] = hb;
            Vl[d * VSTR + s] = __float2bfloat16(e[q] - __bfloat162float(hb));
        }
    }
    __syncthreads();

    const float scale = 0.125f;
    const int b  = bh / HH, h = bh % HH;
    const int rbase = b * TT;

    #pragma unroll
    for (int mi = 0; mi < 2; ++mi) {
        const int tile = (mi == 0) ? wid : 15 - wid;
        const int m_lo = tile * 16;
        const int nkb  = (m_lo >> 6) + 1;
        const int r0 = m_lo + grp, r1 = r0 + 8;

        float o[8][4];
        #pragma unroll
        for (int ni = 0; ni < 8; ++ni)
            #pragma unroll
            for (int q = 0; q < 4; ++q) o[ni][q] = 0.0f;
        float lsum0 = 0.0f, lsum1 = 0.0f;

        for (int kb = 0; kb < nkb; ++kb) {
            float s[8][4];
            #pragma unroll
            for (int ni = 0; ni < 8; ++ni)
                #pragma unroll
                for (int q = 0; q < 4; ++q) s[ni][q] = 0.0f;

            #pragma unroll
            for (int ks = 0; ks < 4; ++ks) {
                const int kofs = ks * 16 + 2 * tig;
                const __nv_bfloat16* qH = Qh + (m_lo + grp) * QSTR + kofs;
                const __nv_bfloat16* qL = Ql + (m_lo + grp) * QSTR + kofs;
                uint32_t aH[4] = { lds32(qH), lds32(qH + 8 * QSTR),
                                   lds32(qH + 8), lds32(qH + 8 * QSTR + 8) };
                uint32_t aL[4] = { lds32(qL), lds32(qL + 8 * QSTR),
                                   lds32(qL + 8), lds32(qL + 8 * QSTR + 8) };
                uint32_t bH[4][4], bL[4][4];
                #pragma unroll
                for (int nb = 0; nb < 4; ++nb) {
                    const __nv_bfloat16* kH = Kh + (kb * 64 + nb * 16 + grp) * QSTR + kofs;
                    const __nv_bfloat16* kL = Kl + (kb * 64 + nb * 16 + grp) * QSTR + kofs;
                    bH[nb][0] = lds32(kH);           bH[nb][1] = lds32(kH + 8);
                    bH[nb][2] = lds32(kH + 8*QSTR);  bH[nb][3] = lds32(kH + 8*QSTR + 8);
                    bL[nb][0] = lds32(kL);           bL[nb][1] = lds32(kL + 8);
                    bL[nb][2] = lds32(kL + 8*QSTR);  bL[nb][3] = lds32(kL + 8*QSTR + 8);
                }
                #pragma unroll
                for (int ni = 0; ni < 8; ++ni) {
                    uint32_t b0h = bH[ni >> 1][(ni & 1) * 2], b1h = bH[ni >> 1][(ni & 1) * 2 + 1];
                    uint32_t b0l = bL[ni >> 1][(ni & 1) * 2], b1l = bL[ni >> 1][(ni & 1) * 2 + 1];
                    mma16816(s[ni], aH, b0h, b1h);
                    mma16816(s[ni], aH, b0l, b1l);
                    mma16816(s[ni], aL, b0h, b1h);
                }
            }

            #pragma unroll
            for (int ni = 0; ni < 8; ++ni) {
                const int c0 = kb * 64 + ni * 8 + 2 * tig, c1 = c0 + 1;
                float e0 = (c0 <= r0) ? __expf(s[ni][0] * scale) : 0.0f;
                float e1 = (c1 <= r0) ? __expf(s[ni][1] * scale) : 0.0f;
                float e2 = (c0 <= r1) ? __expf(s[ni][2] * scale) : 0.0f;
                float e3 = (c1 <= r1) ? __expf(s[ni][3] * scale) : 0.0f;
                lsum0 += e0 + e1;
                lsum1 += e2 + e3;
                s[ni][0] = e0; s[ni][1] = e1; s[ni][2] = e2; s[ni][3] = e3;
            }

            #pragma unroll
            for (int ksv = 0; ksv < 4; ++ksv) {
                uint32_t paH[4], paL[4];
                split_pair(s[2*ksv][0],   s[2*ksv][1],   paH[0], paL[0]);
                split_pair(s[2*ksv][2],   s[2*ksv][3],   paH[1], paL[1]);
                split_pair(s[2*ksv+1][0], s[2*ksv+1][1], paH[2], paL[2]);
                split_pair(s[2*ksv+1][2], s[2*ksv+1][3], paH[3], paL[3]);
                const int colv = kb * 64 + ksv * 16 + 2 * tig;
                uint32_t vbH[4][4], vbL[4][4];
                #pragma unroll
                for (int nb = 0; nb < 4; ++nb) {
                    const __nv_bfloat16* vH = Vh + (nb * 16 + grp) * VSTR + colv;
                    const __nv_bfloat16* vL = Vl + (nb * 16 + grp) * VSTR + colv;
                    vbH[nb][0] = lds32(vH);           vbH[nb][1] = lds32(vH + 8);
                    vbH[nb][2] = lds32(vH + 8*VSTR);  vbH[nb][3] = lds32(vH + 8*VSTR + 8);
                    vbL[nb][0] = lds32(vL);           vbL[nb][1] = lds32(vL + 8);
                    vbL[nb][2] = lds32(vL + 8*VSTR);  vbL[nb][3] = lds32(vL + 8*VSTR + 8);
                }
                #pragma unroll
                for (int ni = 0; ni < 8; ++ni) {
                    uint32_t b0h = vbH[ni >> 1][(ni & 1) * 2], b1h = vbH[ni >> 1][(ni & 1) * 2 + 1];
                    uint32_t b0l = vbL[ni >> 1][(ni & 1) * 2], b1l = vbL[ni >> 1][(ni & 1) * 2 + 1];
                    mma16816(o[ni], paH, b0h, b1h);
                    mma16816(o[ni], paL, b0h, b1h);
                    mma16816(o[ni], paH, b0l, b1l);
                }
            }
        }

        lsum0 += __shfl_xor_sync(0xffffffffu, lsum0, 1);
        lsum0 += __shfl_xor_sync(0xffffffffu, lsum0, 2);
        lsum1 += __shfl_xor_sync(0xffffffffu, lsum1, 1);
        lsum1 += __shfl_xor_sync(0xffffffffu, lsum1, 2);
        const float inv0 = 1.0f / lsum0, inv1 = 1.0f / lsum1;

        #pragma unroll
        for (int ni = 0; ni < 8; ++ni) {
            const int col = h * 64 + ni * 8 + 2 * tig;
            uint32_t hv, lv;
            split_pair(o[ni][0] * inv0, o[ni][1] * inv0, hv, lv);
            *(uint32_t*)(g_Ah + (size_t)(rbase + r0) * CC + col) = hv;
            *(uint32_t*)(g_Al + (size_t)(rbase + r0) * CC + col) = lv;
            split_pair(o[ni][2] * inv1, o[ni][3] * inv1, hv, lv);
            *(uint32_t*)(g_Ah + (size_t)(rbase + r1) * CC + col) = hv;
            *(uint32_t*)(g_Al + (size_t)(rbase + r1) * CC + col) = lv;
        }
    }
}

// ---------------------------------------------------------------------------
extern "C" void kernel_launch(void* const* d_in, const int* in_sizes, int n_in,
                              void* d_out, int out_size)
{
    const float* x  = (const float*)d_in[0];
    const float* Wq = (const float*)d_in[1];
    const float* Wk = (const float*)d_in[2];
    const float* Wv = (const float*)d_in[3];
    const float* Wp = (const float*)d_in[4];
    const float* bp = (const float*)d_in[5];
    float* out = (float*)d_out;

    const int HMMA_SMEM = HS_TOT * (int)sizeof(__nv_bfloat16);    // 55296 B
    const int ATTN_SMEM = AF_TOT * (int)sizeof(__nv_bfloat16);    // 215040 B
    cudaFuncSetAttribute(hmma_gemm, cudaFuncAttributeMaxDynamicSharedMemorySize, HMMA_SMEM);
    cudaFuncSetAttribute(attn_flash, cudaFuncAttributeMaxDynamicSharedMemorySize, ATTN_SMEM);

    conv_x<<<BT*CC/256, 256>>>(x);
    conv_w<<<3*CC*CC/256, 256>>>(Wq, Wk, Wv);
    conv_wp<<<CC*CC/256, 256>>>(Wp);
    hmma_gemm<<<dim3(BT/128, 18), 256, HMMA_SMEM>>>(0, nullptr, nullptr);
    attn_flash<<<BB*HH, 256, ATTN_SMEM>>>();
    hmma_gemm<<<dim3(BT/128, 6), 256, HMMA_SMEM>>>(1, bp, out);
}

// round 15
// speedup vs baseline: 1.0855x; 1.0855x over previous
#include <cuda_runtime.h>
#include <cuda_bf16.h>
#include <cstdint>

#define BB 64
#define TT 256
#define CC 384
#define HH 6
#define DD 64
#define BT (BB*TT)

// Scratch (device globals: allocation-free per harness rules)
__device__ float g_Q[BB*HH*TT*DD];   // [b][h][t][d]
__device__ float g_K[BB*HH*TT*DD];
__device__ float g_V[BB*HH*TT*DD];

// bf16 hi/lo split operands (256B-aligned for cp.async 16B copies)
__device__ __align__(256) __nv_bfloat16 g_Xh[BT*CC],  g_Xl[BT*CC];       // x rows [r][c]
__device__ __align__(256) __nv_bfloat16 g_Wth[3*CC*CC], g_Wtl[3*CC*CC]; // W^T [p][n][k]
__device__ __align__(256) __nv_bfloat16 g_Ah[BT*CC],  g_Al[BT*CC];      // attn out rows
__device__ __align__(256) __nv_bfloat16 g_Wph[CC*CC], g_Wpl[CC*CC];     // Wp^T [n][k]

// ---------------------------------------------------------------------------
__device__ __forceinline__ void mma16816(float* c, const uint32_t* a, uint32_t b0, uint32_t b1) {
    asm volatile("mma.sync.aligned.m16n8k16.row.col.f32.bf16.bf16.f32 "
                 "{%0,%1,%2,%3}, {%4,%5,%6,%7}, {%8,%9}, {%0,%1,%2,%3};"
                 : "+f"(c[0]), "+f"(c[1]), "+f"(c[2]), "+f"(c[3])
                 : "r"(a[0]), "r"(a[1]), "r"(a[2]), "r"(a[3]), "r"(b0), "r"(b1));
}
__device__ __forceinline__ uint32_t lds32(const __nv_bfloat16* p) {
    return *(const uint32_t*)p;
}
__device__ __forceinline__ uint32_t smem_u32(const void* p) {
    uint32_t a;
    asm("{ .reg .u64 t; cvta.to.shared.u64 t, %1; cvt.u32.u64 %0, t; }" : "=r"(a) : "l"(p));
    return a;
}
__device__ __forceinline__ void cpasync16(uint32_t dst, const void* src) {
    asm volatile("cp.async.cg.shared.global [%0], [%1], 16;" :: "r"(dst), "l"(src));
}
// split (a,b) fp32 pair into packed bf16x2 hi and lo
__device__ __forceinline__ void split_pair(float a, float b, uint32_t& h, uint32_t& l) {
    __nv_bfloat16 ah = __float2bfloat16(a), bh = __float2bfloat16(b);
    __nv_bfloat162 hv; hv.x = ah; hv.y = bh;
    h = *(uint32_t*)&hv;
    __nv_bfloat162 lv = __floats2bfloat162_rn(a - __bfloat162float(ah),
                                              b - __bfloat162float(bh));
    l = *(uint32_t*)&lv;
}

// ---------------------------------------------------------------------------
// Prep kernels
// ---------------------------------------------------------------------------
__global__ __launch_bounds__(256) void conv_x(const float* __restrict__ x) {
    int i = blockIdx.x * 256 + threadIdx.x;
    float v = x[i];
    __nv_bfloat16 h = __float2bfloat16(v);
    g_Xh[i] = h;
    g_Xl[i] = __float2bfloat16(v - __bfloat162float(h));
}
__global__ __launch_bounds__(256) void conv_w(
    const float* __restrict__ Wq, const float* __restrict__ Wk, const float* __restrict__ Wv)
{
    int i = blockIdx.x * 256 + threadIdx.x;          // 3*384*384
    int p = i / (CC * CC);
    int rem = i - p * CC * CC;
    int n = rem / CC, k = rem - n * CC;
    int h = n >> 6, d = n & 63;
    const float* W = (p == 0 ? Wq : (p == 1 ? Wk : Wv));
    float v = W[(h * CC + k) * DD + d];
    __nv_bfloat16 hi = __float2bfloat16(v);
    g_Wth[i] = hi;
    g_Wtl[i] = __float2bfloat16(v - __bfloat162float(hi));
}
__global__ __launch_bounds__(256) void conv_wp(const float* __restrict__ Wp) {
    int i = blockIdx.x * 256 + threadIdx.x;          // 384*384
    int n = i / CC, k = i - n * CC;
    float v = Wp[k * CC + n];
    __nv_bfloat16 hi = __float2bfloat16(v);
    g_Wph[i] = hi;
    g_Wpl[i] = __float2bfloat16(v - __bfloat162float(hi));
}

// ---------------------------------------------------------------------------
// HMMA GEMM with cp.async CHUNK PIPELINE (round 13):
// smem double buffer (2x55KB), prefetch chunk ch+2 during MMA of chunk ch.
// Pass-major MMA ordering (8 independent accumulators between RAW deps).
// ---------------------------------------------------------------------------
#define ASTR 72
#define HS_AH 0
#define HS_AL (128*ASTR)
#define HS_BH (2*128*ASTR)
#define HS_BL (2*128*ASTR + 64*ASTR)
#define HS_TOT (2*128*ASTR + 2*64*ASTR)   // 27648 elems = 55296 B per buffer

#define LOAD_FRAGS(BUF, KS) do {                                               \
    const int kofs_ = (KS) * 16 + 2 * tig;                                     \
    _Pragma("unroll")                                                          \
    for (int mi_ = 0; mi_ < 2; ++mi_) {                                        \
        const __nv_bfloat16* pH = AsH + (wm + mi_ * 16 + grp) * ASTR + kofs_;  \
        const __nv_bfloat16* pL = AsL + (wm + mi_ * 16 + grp) * ASTR + kofs_;  \
        fah[BUF][mi_][0] = lds32(pH);                                          \
        fah[BUF][mi_][1] = lds32(pH + 8 * ASTR);                               \
        fah[BUF][mi_][2] = lds32(pH + 8);                                      \
        fah[BUF][mi_][3] = lds32(pH + 8 * ASTR + 8);                           \
        fal[BUF][mi_][0] = lds32(pL);                                          \
        fal[BUF][mi_][1] = lds32(pL + 8 * ASTR);                               \
        fal[BUF][mi_][2] = lds32(pL + 8);                                      \
        fal[BUF][mi_][3] = lds32(pL + 8 * ASTR + 8);                           \
    }                                                                          \
    _Pragma("unroll")                                                          \
    for (int nb_ = 0; nb_ < 2; ++nb_) {                                       \
        const __nv_bfloat16* pH = BsH + (wn + nb_ * 16 + grp) * ASTR + kofs_;  \
        const __nv_bfloat16* pL = BsL + (wn + nb_ * 16 + grp) * ASTR + kofs_;  \
        fbh[BUF][nb_][0] = lds32(pH);                                          \
        fbh[BUF][nb_][1] = lds32(pH + 8);                                      \
        fbh[BUF][nb_][2] = lds32(pH + 8 * ASTR);                               \
        fbh[BUF][nb_][3] = lds32(pH + 8 * ASTR + 8);                           \
        fbl[BUF][nb_][0] = lds32(pL);                                          \
        fbl[BUF][nb_][1] = lds32(pL + 8);                                      \
        fbl[BUF][nb_][2] = lds32(pL + 8 * ASTR);                               \
        fbl[BUF][nb_][3] = lds32(pL + 8 * ASTR + 8);                           \
    }                                                                          \
} while (0)

__global__ __launch_bounds__(256, 2) void hmma_gemm(
    int mode, const float* __restrict__ bias, float* __restrict__ outp)
{
    extern __shared__ __nv_bfloat16 hsm[];
    const uint32_t sbase = smem_u32(hsm);

    const int tid  = threadIdx.x;
    const int lane = tid & 31;
    const int wid  = tid >> 5;
    const int m0   = blockIdx.x * 128;

    int p = 0, h2;
    const __nv_bfloat16 *Ah, *Al, *Bh, *Bl;
    float* O;
    if (mode == 0) {
        p = blockIdx.y / 6; h2 = blockIdx.y % 6;
        Ah = g_Xh; Al = g_Xl;
        Bh = g_Wth + p * CC * CC + h2 * 64 * CC;
        Bl = g_Wtl + p * CC * CC + h2 * 64 * CC;
        O  = (p == 0 ? g_Q : (p == 1 ? g_K : g_V));
    } else {
        h2 = blockIdx.y;
        Ah = g_Ah; Al = g_Al;
        Bh = g_Wph + h2 * 64 * CC;
        Bl = g_Wpl + h2 * 64 * CC;
        O  = outp;
    }

    const int wm = (wid & 3) * 32;
    const int wn = (wid >> 2) * 32;
    const int grp = lane >> 2;
    const int tig = lane & 3;

    // cp.async issue of one chunk into buffer buf
    auto issue = [&](int buf, int ch) {
        const int kb = ch * 64;
        const uint32_t b0 = sbase + (uint32_t)buf * (HS_TOT * 2);
        #pragma unroll
        for (int j = 0; j < 4; ++j) {
            int i = tid + j * 256;
            int row = i >> 3, q8 = i & 7;
            uint32_t so = (uint32_t)(row * ASTR + q8 * 8) * 2;
            const int gi = (m0 + row) * CC + kb + q8 * 8;
            cpasync16(b0 + HS_AH * 2 + so, Ah + gi);
            cpasync16(b0 + HS_AL * 2 + so, Al + gi);
        }
        #pragma unroll
        for (int j = 0; j < 2; ++j) {
            int i = tid + j * 256;
            int row = i >> 3, q8 = i & 7;
            uint32_t so = (uint32_t)(row * ASTR + q8 * 8) * 2;
            const int gi = row * CC + kb + q8 * 8;
            cpasync16(b0 + HS_BH * 2 + so, Bh + gi);
            cpasync16(b0 + HS_BL * 2 + so, Bl + gi);
        }
        asm volatile("cp.async.commit_group;" ::: "memory");
    };

    float c[2][4][4] = {};
    uint32_t fah[2][2][4], fal[2][2][4], fbh[2][2][4], fbl[2][2][4];

    issue(0, 0);
    issue(1, 1);

    #pragma unroll
    for (int ch = 0; ch < 6; ++ch) {
        const int buf = ch & 1;
        if (ch < 4) asm volatile("cp.async.wait_group 1;" ::: "memory");
        else        asm volatile("cp.async.wait_group 0;" ::: "memory");
        __syncthreads();

        __nv_bfloat16* AsH = hsm + buf * HS_TOT + HS_AH;
        __nv_bfloat16* AsL = hsm + buf * HS_TOT + HS_AL;
        __nv_bfloat16* BsH = hsm + buf * HS_TOT + HS_BH;
        __nv_bfloat16* BsL = hsm + buf * HS_TOT + HS_BL;

        LOAD_FRAGS(0, 0);
        #pragma unroll
        for (int ks = 0; ks < 4; ++ks) {
            const int cur = ks & 1;
            if (ks < 3) { LOAD_FRAGS(!cur, ks + 1); }
            // pass-major: 8 independent accumulators between RAW-dependent MMAs
            #pragma unroll
            for (int mi = 0; mi < 2; ++mi)
                #pragma unroll
                for (int ni = 0; ni < 4; ++ni)
                    mma16816(c[mi][ni], fah[cur][mi],
                             fbh[cur][ni >> 1][(ni & 1) * 2],
                             fbh[cur][ni >> 1][(ni & 1) * 2 + 1]);
            #pragma unroll
            for (int mi = 0; mi < 2; ++mi)
                #pragma unroll
                for (int ni = 0; ni < 4; ++ni)
                    mma16816(c[mi][ni], fah[cur][mi],
                             fbl[cur][ni >> 1][(ni & 1) * 2],
                             fbl[cur][ni >> 1][(ni & 1) * 2 + 1]);
            #pragma unroll
            for (int mi = 0; mi < 2; ++mi)
                #pragma unroll
                for (int ni = 0; ni < 4; ++ni)
                    mma16816(c[mi][ni], fal[cur][mi],
                             fbh[cur][ni >> 1][(ni & 1) * 2],
                             fbh[cur][ni >> 1][(ni & 1) * 2 + 1]);
        }
        __syncthreads();
        if (ch + 2 < 6) issue(buf, ch + 2);
    }

    #pragma unroll
    for (int mi = 0; mi < 2; ++mi) {
        #pragma unroll
        for (int ni = 0; ni < 4; ++ni) {
            int row0 = m0 + wm + mi * 16 + grp;
            int col  = wn + ni * 8 + tig * 2;
            if (mode == 0) {
                int b0i = row0 >> 8, t0 = row0 & 255;
                int r1 = row0 + 8, b1i = r1 >> 8, t1 = r1 & 255;
                *(float2*)(O + ((b0i * HH + h2) * TT + t0) * DD + col) =
                    make_float2(c[mi][ni][0], c[mi][ni][1]);
                *(float2*)(O + ((b1i * HH + h2) * TT + t1) * DD + col) =
                    make_float2(c[mi][ni][2], c[mi][ni][3]);
            } else {
                int n = h2 * 64 + col;
                float2 bv = *(const float2*)(bias + n);
                *(float2*)(O + (size_t)row0 * CC + n) =
                    make_float2(c[mi][ni][0] + bv.x, c[mi][ni][1] + bv.y);
                *(float2*)(O + (size_t)(row0 + 8) * CC + n) =
                    make_float2(c[mi][ni][2] + bv.x, c[mi][ni][3] + bv.y);
            }
        }
    }
}

// ---------------------------------------------------------------------------
// Flash-style HMMA causal attention (validated round 9, unchanged).
// ---------------------------------------------------------------------------
#define QSTR 72
#define VSTR 264
#define AF_QH 0
#define AF_QL (256*QSTR)
#define AF_KH (2*256*QSTR)
#define AF_KL (3*256*QSTR)
#define AF_VH (4*256*QSTR)
#define AF_VL (4*256*QSTR + 64*VSTR)
#define AF_TOT (4*256*QSTR + 2*64*VSTR)   // 107520 elems = 215040 B

__global__ __launch_bounds__(256) void attn_flash()
{
    extern __shared__ __nv_bfloat16 asm_[];
    __nv_bfloat16* Qh = asm_ + AF_QH;
    __nv_bfloat16* Ql = asm_ + AF_QL;
    __nv_bfloat16* Kh = asm_ + AF_KH;
    __nv_bfloat16* Kl = asm_ + AF_KL;
    __nv_bfloat16* Vh = asm_ + AF_VH;
    __nv_bfloat16* Vl = asm_ + AF_VL;

    const int bh  = blockIdx.x;
    const int tid = threadIdx.x;
    const int lane = tid & 31;
    const int wid  = tid >> 5;
    const int grp  = lane >> 2;
    const int tig  = lane & 3;

    const float4* Qg = (const float4*)(g_Q + (size_t)bh * TT * DD);
    const float4* Kg = (const float4*)(g_K + (size_t)bh * TT * DD);
    const float4* Vg = (const float4*)(g_V + (size_t)bh * TT * DD);
    #pragma unroll
    for (int j = 0; j < 16; ++j) {
        int i4 = tid + j * 256;
        int row = i4 >> 4, c4 = (i4 & 15) * 4;
        float4 qv = Qg[i4];
        uint32_t h0, l0, h1, l1;
        split_pair(qv.x, qv.y, h0, l0);
        split_pair(qv.z, qv.w, h1, l1);
        *(uint32_t*)(Qh + row * QSTR + c4)     = h0;
        *(uint32_t*)(Qh + row * QSTR + c4 + 2) = h1;
        *(uint32_t*)(Ql + row * QSTR + c4)     = l0;
        *(uint32_t*)(Ql + row * QSTR + c4 + 2) = l1;
        float4 kv = Kg[i4];
        split_pair(kv.x, kv.y, h0, l0);
        split_pair(kv.z, kv.w, h1, l1);
        *(uint32_t*)(Kh + row * QSTR + c4)     = h0;
        *(uint32_t*)(Kh + row * QSTR + c4 + 2) = h1;
        *(uint32_t*)(Kl + row * QSTR + c4)     = l0;
        *(uint32_t*)(Kl + row * QSTR + c4 + 2) = l1;
    }
    #pragma unroll
    for (int j = 0; j < 16; ++j) {
        int i4 = tid + j * 256;
        int d4 = i4 >> 8, s = i4 & 255;
        float4 vv = Vg[s * 16 + d4];
        float e[4] = {vv.x, vv.y, vv.z, vv.w};
        #pragma unroll
        for (int q = 0; q < 4; ++q) {
            int d = d4 * 4 + q;
            __nv_bfloat16 hb = __float2bfloat16(e[q]);
            Vh[d * VSTR + s] = hb;
            Vl[d * VSTR + s] = __float2bfloat16(e[q] - __bfloat162float(hb));
        }
    }
    __syncthreads();

    const float scale = 0.125f;
    const int b  = bh / HH, h = bh % HH;
    const int rbase = b * TT;

    #pragma unroll
    for (int mi = 0; mi < 2; ++mi) {
        const int tile = (mi == 0) ? wid : 15 - wid;
        const int m_lo = tile * 16;
        const int nkb  = (m_lo >> 6) + 1;
        const int r0 = m_lo + grp, r1 = r0 + 8;

        float o[8][4];
        #pragma unroll
        for (int ni = 0; ni < 8; ++ni)
            #pragma unroll
            for (int q = 0; q < 4; ++q) o[ni][q] = 0.0f;
        float lsum0 = 0.0f, lsum1 = 0.0f;

        for (int kb = 0; kb < nkb; ++kb) {
            float s[8][4];
            #pragma unroll
            for (int ni = 0; ni < 8; ++ni)
                #pragma unroll
                for (int q = 0; q < 4; ++q) s[ni][q] = 0.0f;

            #pragma unroll
            for (int ks = 0; ks < 4; ++ks) {
                const int kofs = ks * 16 + 2 * tig;
                const __nv_bfloat16* qH = Qh + (m_lo + grp) * QSTR + kofs;
                const __nv_bfloat16* qL = Ql + (m_lo + grp) * QSTR + kofs;
                uint32_t aH[4] = { lds32(qH), lds32(qH + 8 * QSTR),
                                   lds32(qH + 8), lds32(qH + 8 * QSTR + 8) };
                uint32_t aL[4] = { lds32(qL), lds32(qL + 8 * QSTR),
                                   lds32(qL + 8), lds32(qL + 8 * QSTR + 8) };
                uint32_t bH[4][4], bL[4][4];
                #pragma unroll
                for (int nb = 0; nb < 4; ++nb) {
                    const __nv_bfloat16* kH = Kh + (kb * 64 + nb * 16 + grp) * QSTR + kofs;
                    const __nv_bfloat16* kL = Kl + (kb * 64 + nb * 16 + grp) * QSTR + kofs;
                    bH[nb][0] = lds32(kH);           bH[nb][1] = lds32(kH + 8);
                    bH[nb][2] = lds32(kH + 8*QSTR);  bH[nb][3] = lds32(kH + 8*QSTR + 8);
                    bL[nb][0] = lds32(kL);           bL[nb][1] = lds32(kL + 8);
                    bL[nb][2] = lds32(kL + 8*QSTR);  bL[nb][3] = lds32(kL + 8*QSTR + 8);
                }
                #pragma unroll
                for (int ni = 0; ni < 8; ++ni) {
                    uint32_t b0h = bH[ni >> 1][(ni & 1) * 2], b1h = bH[ni >> 1][(ni & 1) * 2 + 1];
                    uint32_t b0l = bL[ni >> 1][(ni & 1) * 2], b1l = bL[ni >> 1][(ni & 1) * 2 + 1];
                    mma16816(s[ni], aH, b0h, b1h);
                    mma16816(s[ni], aH, b0l, b1l);
                    mma16816(s[ni], aL, b0h, b1h);
                }
            }

            #pragma unroll
            for (int ni = 0; ni < 8; ++ni) {
                const int c0 = kb * 64 + ni * 8 + 2 * tig, c1 = c0 + 1;
                float e0 = (c0 <= r0) ? __expf(s[ni][0] * scale) : 0.0f;
                float e1 = (c1 <= r0) ? __expf(s[ni][1] * scale) : 0.0f;
                float e2 = (c0 <= r1) ? __expf(s[ni][2] * scale) : 0.0f;
                float e3 = (c1 <= r1) ? __expf(s[ni][3] * scale) : 0.0f;
                lsum0 += e0 + e1;
                lsum1 += e2 + e3;
                s[ni][0] = e0; s[ni][1] = e1; s[ni][2] = e2; s[ni][3] = e3;
            }

            #pragma unroll
            for (int ksv = 0; ksv < 4; ++ksv) {
                uint32_t paH[4], paL[4];
                split_pair(s[2*ksv][0],   s[2*ksv][1],   paH[0], paL[0]);
                split_pair(s[2*ksv][2],   s[2*ksv][3],   paH[1], paL[1]);
                split_pair(s[2*ksv+1][0], s[2*ksv+1][1], paH[2], paL[2]);
                split_pair(s[2*ksv+1][2], s[2*ksv+1][3], paH[3], paL[3]);
                const int colv = kb * 64 + ksv * 16 + 2 * tig;
                uint32_t vbH[4][4], vbL[4][4];
                #pragma unroll
                for (int nb = 0; nb < 4; ++nb) {
                    const __nv_bfloat16* vH = Vh + (nb * 16 + grp) * VSTR + colv;
                    const __nv_bfloat16* vL = Vl + (nb * 16 + grp) * VSTR + colv;
                    vbH[nb][0] = lds32(vH);           vbH[nb][1] = lds32(vH + 8);
                    vbH[nb][2] = lds32(vH + 8*VSTR);  vbH[nb][3] = lds32(vH + 8*VSTR + 8);
                    vbL[nb][0] = lds32(vL);           vbL[nb][1] = lds32(vL + 8);
                    vbL[nb][2] = lds32(vL + 8*VSTR);  vbL[nb][3] = lds32(vL + 8*VSTR + 8);
                }
                #pragma unroll
                for (int ni = 0; ni < 8; ++ni) {
                    uint32_t b0h = vbH[ni >> 1][(ni & 1) * 2], b1h = vbH[ni >> 1][(ni & 1) * 2 + 1];
                    uint32_t b0l = vbL[ni >> 1][(ni & 1) * 2], b1l = vbL[ni >> 1][(ni & 1) * 2 + 1];
                    mma16816(o[ni], paH, b0h, b1h);
                    mma16816(o[ni], paL, b0h, b1h);
                    mma16816(o[ni], paH, b0l, b1l);
                }
            }
        }

        lsum0 += __shfl_xor_sync(0xffffffffu, lsum0, 1);
        lsum0 += __shfl_xor_sync(0xffffffffu, lsum0, 2);
        lsum1 += __shfl_xor_sync(0xffffffffu, lsum1, 1);
        lsum1 += __shfl_xor_sync(0xffffffffu, lsum1, 2);
        const float inv0 = 1.0f / lsum0, inv1 = 1.0f / lsum1;

        #pragma unroll
        for (int ni = 0; ni < 8; ++ni) {
            const int col = h * 64 + ni * 8 + 2 * tig;
            uint32_t hv, lv;
            split_pair(o[ni][0] * inv0, o[ni][1] * inv0, hv, lv);
            *(uint32_t*)(g_Ah + (size_t)(rbase + r0) * CC + col) = hv;
            *(uint32_t*)(g_Al + (size_t)(rbase + r0) * CC + col) = lv;
            split_pair(o[ni][2] * inv1, o[ni][3] * inv1, hv, lv);
            *(uint32_t*)(g_Ah + (size_t)(rbase + r1) * CC + col) = hv;
            *(uint32_t*)(g_Al + (size_t)(rbase + r1) * CC + col) = lv;
        }
    }
}

// ---------------------------------------------------------------------------
extern "C" void kernel_launch(void* const* d_in, const int* in_sizes, int n_in,
                              void* d_out, int out_size)
{
    const float* x  = (const float*)d_in[0];
    const float* Wq = (const float*)d_in[1];
    const float* Wk = (const float*)d_in[2];
    const float* Wv = (const float*)d_in[3];
    const float* Wp = (const float*)d_in[4];
    const float* bp = (const float*)d_in[5];
    float* out = (float*)d_out;

    const int HMMA_SMEM = 2 * HS_TOT * (int)sizeof(__nv_bfloat16);  // 110592 B
    const int ATTN_SMEM = AF_TOT * (int)sizeof(__nv_bfloat16);      // 215040 B
    cudaFuncSetAttribute(hmma_gemm, cudaFuncAttributeMaxDynamicSharedMemorySize, HMMA_SMEM);
    cudaFuncSetAttribute(attn_flash, cudaFuncAttributeMaxDynamicSharedMemorySize, ATTN_SMEM);

    conv_x<<<BT*CC/256, 256>>>(x);
    conv_w<<<3*CC*CC/256, 256>>>(Wq, Wk, Wv);
    conv_wp<<<CC*CC/256, 256>>>(Wp);
    hmma_gemm<<<dim3(BT/128, 18), 256, HMMA_SMEM>>>(0, nullptr, nullptr);
    attn_flash<<<BB*HH, 256, ATTN_SMEM>>>();
    hmma_gemm<<<dim3(BT/128, 6), 256, HMMA_SMEM>>>(1, bp, out);
}

// round 16
// speedup vs baseline: 1.1369x; 1.0473x over previous
#include <cuda_runtime.h>
#include <cuda_bf16.h>
#include <cstdint>

#define BB 64
#define TT 256
#define CC 384
#define HH 6
#define DD 64
#define BT (BB*TT)

// Scratch (device globals: allocation-free per harness rules)
__device__ float g_Q[BB*HH*TT*DD];   // [b][h][t][d]
__device__ float g_K[BB*HH*TT*DD];
__device__ float g_V[BB*HH*TT*DD];

// bf16 hi/lo split operands (256B-aligned for cp.async 16B copies)
__device__ __align__(256) __nv_bfloat16 g_Xh[BT*CC],  g_Xl[BT*CC];       // x rows [r][c]
__device__ __align__(256) __nv_bfloat16 g_Wth[3*CC*CC], g_Wtl[3*CC*CC]; // W^T [p][n][k]
__device__ __align__(256) __nv_bfloat16 g_Ah[BT*CC],  g_Al[BT*CC];      // attn out rows
__device__ __align__(256) __nv_bfloat16 g_Wph[CC*CC], g_Wpl[CC*CC];     // Wp^T [n][k]

// ---------------------------------------------------------------------------
__device__ __forceinline__ void mma16816(float* c, const uint32_t* a, uint32_t b0, uint32_t b1) {
    asm volatile("mma.sync.aligned.m16n8k16.row.col.f32.bf16.bf16.f32 "
                 "{%0,%1,%2,%3}, {%4,%5,%6,%7}, {%8,%9}, {%0,%1,%2,%3};"
                 : "+f"(c[0]), "+f"(c[1]), "+f"(c[2]), "+f"(c[3])
                 : "r"(a[0]), "r"(a[1]), "r"(a[2]), "r"(a[3]), "r"(b0), "r"(b1));
}
__device__ __forceinline__ void ldsm4(uint32_t& r0, uint32_t& r1, uint32_t& r2, uint32_t& r3,
                                      uint32_t addr) {
    asm volatile("ldmatrix.sync.aligned.m8n8.x4.shared.b16 {%0,%1,%2,%3}, [%4];"
                 : "=r"(r0), "=r"(r1), "=r"(r2), "=r"(r3) : "r"(addr));
}
__device__ __forceinline__ uint32_t smem_u32(const void* p) {
    uint32_t a;
    asm("{ .reg .u64 t; cvta.to.shared.u64 t, %1; cvt.u32.u64 %0, t; }" : "=r"(a) : "l"(p));
    return a;
}
__device__ __forceinline__ void cpasync16(uint32_t dst, const void* src) {
    asm volatile("cp.async.cg.shared.global [%0], [%1], 16;" :: "r"(dst), "l"(src));
}
// split (a,b) fp32 pair into packed bf16x2 hi and lo
__device__ __forceinline__ void split_pair(float a, float b, uint32_t& h, uint32_t& l) {
    __nv_bfloat16 ah = __float2bfloat16(a), bh = __float2bfloat16(b);
    __nv_bfloat162 hv; hv.x = ah; hv.y = bh;
    h = *(uint32_t*)&hv;
    __nv_bfloat162 lv = __floats2bfloat162_rn(a - __bfloat162float(ah),
                                              b - __bfloat162float(bh));
    l = *(uint32_t*)&lv;
}

// ---------------------------------------------------------------------------
// Prep kernels
// ---------------------------------------------------------------------------
__global__ __launch_bounds__(256) void conv_x(const float* __restrict__ x) {
    int i = blockIdx.x * 256 + threadIdx.x;
    float v = x[i];
    __nv_bfloat16 h = __float2bfloat16(v);
    g_Xh[i] = h;
    g_Xl[i] = __float2bfloat16(v - __bfloat162float(h));
}
__global__ __launch_bounds__(256) void conv_w(
    const float* __restrict__ Wq, const float* __restrict__ Wk, const float* __restrict__ Wv)
{
    int i = blockIdx.x * 256 + threadIdx.x;          // 3*384*384
    int p = i / (CC * CC);
    int rem = i - p * CC * CC;
    int n = rem / CC, k = rem - n * CC;
    int h = n >> 6, d = n & 63;
    const float* W = (p == 0 ? Wq : (p == 1 ? Wk : Wv));
    float v = W[(h * CC + k) * DD + d];
    __nv_bfloat16 hi = __float2bfloat16(v);
    g_Wth[i] = hi;
    g_Wtl[i] = __float2bfloat16(v - __bfloat162float(hi));
}
__global__ __launch_bounds__(256) void conv_wp(const float* __restrict__ Wp) {
    int i = blockIdx.x * 256 + threadIdx.x;          // 384*384
    int n = i / CC, k = i - n * CC;
    float v = Wp[k * CC + n];
    __nv_bfloat16 hi = __float2bfloat16(v);
    g_Wph[i] = hi;
    g_Wpl[i] = __float2bfloat16(v - __bfloat162float(hi));
}

// ---------------------------------------------------------------------------
// HMMA GEMM with cp.async chunk pipeline + ldmatrix.x4 fragment loads.
// Layout unchanged (stride-72 rows = 144 B ≡ 4 words mod 32 -> conflict-free
// for both 16B stores and ldmatrix 8-row wavefronts). Canonical m8n8.x4 lane
// address mapping reproduces the exact coordinate-load fragments (r5≡r6).
// ---------------------------------------------------------------------------
#define ASTR 72
#define HS_AH 0
#define HS_AL (128*ASTR)
#define HS_BH (2*128*ASTR)
#define HS_BL (2*128*ASTR + 64*ASTR)
#define HS_TOT (2*128*ASTR + 2*64*ASTR)   // 27648 elems = 55296 B per buffer

// ldmatrix-based fragment load: 8 LDSM replace 32 LDS.32
#define LOAD_FRAGS(BUF, KS) do {                                               \
    const uint32_t kb_ = (KS) * 32;                                            \
    _Pragma("unroll")                                                          \
    for (int mi_ = 0; mi_ < 2; ++mi_) {                                        \
        uint32_t ra_ = smb + (uint32_t)((wm + mi_ * 16 + rowA) * 144) + kb_ + kselA; \
        ldsm4(fah[BUF][mi_][0], fah[BUF][mi_][1], fah[BUF][mi_][2], fah[BUF][mi_][3], \
              ra_ + HS_AH * 2);                                                \
        ldsm4(fal[BUF][mi_][0], fal[BUF][mi_][1], fal[BUF][mi_][2], fal[BUF][mi_][3], \
              ra_ + HS_AL * 2);                                                \
    }                                                                          \
    _Pragma("unroll")                                                          \
    for (int nb_ = 0; nb_ < 2; ++nb_) {                                        \
        uint32_t rb_ = smb + (uint32_t)((wn + nb_ * 16 + rowB) * 144) + kb_ + kselB; \
        ldsm4(fbh[BUF][nb_][0], fbh[BUF][nb_][1], fbh[BUF][nb_][2], fbh[BUF][nb_][3], \
              rb_ + HS_BH * 2);                                                \
        ldsm4(fbl[BUF][nb_][0], fbl[BUF][nb_][1], fbl[BUF][nb_][2], fbl[BUF][nb_][3], \
              rb_ + HS_BL * 2);                                                \
    }                                                                          \
} while (0)

__global__ __launch_bounds__(256, 2) void hmma_gemm(
    int mode, const float* __restrict__ bias, float* __restrict__ outp)
{
    extern __shared__ __nv_bfloat16 hsm[];
    const uint32_t sbase = smem_u32(hsm);

    const int tid  = threadIdx.x;
    const int lane = tid & 31;
    const int wid  = tid >> 5;
    const int m0   = blockIdx.x * 128;

    int p = 0, h2;
    const __nv_bfloat16 *Ah, *Al, *Bh, *Bl;
    float* O;
    if (mode == 0) {
        p = blockIdx.y / 6; h2 = blockIdx.y % 6;
        Ah = g_Xh; Al = g_Xl;
        Bh = g_Wth + p * CC * CC + h2 * 64 * CC;
        Bl = g_Wtl + p * CC * CC + h2 * 64 * CC;
        O  = (p == 0 ? g_Q : (p == 1 ? g_K : g_V));
    } else {
        h2 = blockIdx.y;
        Ah = g_Ah; Al = g_Al;
        Bh = g_Wph + h2 * 64 * CC;
        Bl = g_Wpl + h2 * 64 * CC;
        O  = outp;
    }

    const int wm = (wid & 3) * 32;
    const int wn = (wid >> 2) * 32;
    const int grp = lane >> 2;
    const int tig = lane & 3;

    // ldmatrix per-lane constants
    const int rowA  = lane & 15;                         // A: row within m16
    const uint32_t kselA = (uint32_t)((lane >> 4) * 16); // +16B for k8..15 mats
    const int rowB  = (lane & 7) + ((lane >> 4) << 3);   // B: +8 rows for lanes>=16
    const uint32_t kselB = (uint32_t)(((lane >> 3) & 1) * 16); // +16B if lane&8

    // cp.async issue of one chunk into buffer buf
    auto issue = [&](int buf, int ch) {
        const int kb = ch * 64;
        const uint32_t b0 = sbase + (uint32_t)buf * (HS_TOT * 2);
        #pragma unroll
        for (int j = 0; j < 4; ++j) {
            int i = tid + j * 256;
            int row = i >> 3, q8 = i & 7;
            uint32_t so = (uint32_t)(row * ASTR + q8 * 8) * 2;
            const int gi = (m0 + row) * CC + kb + q8 * 8;
            cpasync16(b0 + HS_AH * 2 + so, Ah + gi);
            cpasync16(b0 + HS_AL * 2 + so, Al + gi);
        }
        #pragma unroll
        for (int j = 0; j < 2; ++j) {
            int i = tid + j * 256;
            int row = i >> 3, q8 = i & 7;
            uint32_t so = (uint32_t)(row * ASTR + q8 * 8) * 2;
            const int gi = row * CC + kb + q8 * 8;
            cpasync16(b0 + HS_BH * 2 + so, Bh + gi);
            cpasync16(b0 + HS_BL * 2 + so, Bl + gi);
        }
        asm volatile("cp.async.commit_group;" ::: "memory");
    };

    float c[2][4][4] = {};
    uint32_t fah[2][2][4], fal[2][2][4], fbh[2][2][4], fbl[2][2][4];

    issue(0, 0);
    issue(1, 1);

    #pragma unroll
    for (int ch = 0; ch < 6; ++ch) {
        const int buf = ch & 1;
        if (ch < 4) asm volatile("cp.async.wait_group 1;" ::: "memory");
        else        asm volatile("cp.async.wait_group 0;" ::: "memory");
        __syncthreads();

        const uint32_t smb = sbase + (uint32_t)buf * (HS_TOT * 2);

        LOAD_FRAGS(0, 0);
        #pragma unroll
        for (int ks = 0; ks < 4; ++ks) {
            const int cur = ks & 1;
            if (ks < 3) { LOAD_FRAGS(!cur, ks + 1); }
            // pass-major: 8 independent accumulators between RAW-dependent MMAs
            #pragma unroll
            for (int mi = 0; mi < 2; ++mi)
                #pragma unroll
                for (int ni = 0; ni < 4; ++ni)
                    mma16816(c[mi][ni], fah[cur][mi],
                             fbh[cur][ni >> 1][(ni & 1) * 2],
                             fbh[cur][ni >> 1][(ni & 1) * 2 + 1]);
            #pragma unroll
            for (int mi = 0; mi < 2; ++mi)
                #pragma unroll
                for (int ni = 0; ni < 4; ++ni)
                    mma16816(c[mi][ni], fah[cur][mi],
                             fbl[cur][ni >> 1][(ni & 1) * 2],
                             fbl[cur][ni >> 1][(ni & 1) * 2 + 1]);
            #pragma unroll
            for (int mi = 0; mi < 2; ++mi)
                #pragma unroll
                for (int ni = 0; ni < 4; ++ni)
                    mma16816(c[mi][ni], fal[cur][mi],
                             fbh[cur][ni >> 1][(ni & 1) * 2],
                             fbh[cur][ni >> 1][(ni & 1) * 2 + 1]);
        }
        __syncthreads();
        if (ch + 2 < 6) issue(buf, ch + 2);
    }

    #pragma unroll
    for (int mi = 0; mi < 2; ++mi) {
        #pragma unroll
        for (int ni = 0; ni < 4; ++ni) {
            int row0 = m0 + wm + mi * 16 + grp;
            int col  = wn + ni * 8 + tig * 2;
            if (mode == 0) {
                int b0i = row0 >> 8, t0 = row0 & 255;
                int r1 = row0 + 8, b1i = r1 >> 8, t1 = r1 & 255;
                *(float2*)(O + ((b0i * HH + h2) * TT + t0) * DD + col) =
                    make_float2(c[mi][ni][0], c[mi][ni][1]);
                *(float2*)(O + ((b1i * HH + h2) * TT + t1) * DD + col) =
                    make_float2(c[mi][ni][2], c[mi][ni][3]);
            } else {
                int n = h2 * 64 + col;
                float2 bv = *(const float2*)(bias + n);
                *(float2*)(O + (size_t)row0 * CC + n) =
                    make_float2(c[mi][ni][0] + bv.x, c[mi][ni][1] + bv.y);
                *(float2*)(O + (size_t)(row0 + 8) * CC + n) =
                    make_float2(c[mi][ni][2] + bv.x, c[mi][ni][3] + bv.y);
            }
        }
    }
}

// ---------------------------------------------------------------------------
// Flash-style HMMA causal attention, now with ldmatrix.x4 fragment loads.
// Same canonical mappings; V B-frags use stride VSTR (528 B rows, also
// conflict-free). Masking/softmax/epilogue untouched.
// ---------------------------------------------------------------------------
#define QSTR 72
#define VSTR 264
#define AF_QH 0
#define AF_QL (256*QSTR)
#define AF_KH (2*256*QSTR)
#define AF_KL (3*256*QSTR)
#define AF_VH (4*256*QSTR)
#define AF_VL (4*256*QSTR + 64*VSTR)
#define AF_TOT (4*256*QSTR + 2*64*VSTR)   // 107520 elems = 215040 B

__global__ __launch_bounds__(256) void attn_flash()
{
    extern __shared__ __nv_bfloat16 asm_[];
    __nv_bfloat16* Qh = asm_ + AF_QH;
    __nv_bfloat16* Ql = asm_ + AF_QL;
    __nv_bfloat16* Kh = asm_ + AF_KH;
    __nv_bfloat16* Kl = asm_ + AF_KL;
    __nv_bfloat16* Vh = asm_ + AF_VH;
    __nv_bfloat16* Vl = asm_ + AF_VL;
    const uint32_t ab = smem_u32(asm_);
    const uint32_t uQh = ab + AF_QH * 2, uQl = ab + AF_QL * 2;
    const uint32_t uKh = ab + AF_KH * 2, uKl = ab + AF_KL * 2;
    const uint32_t uVh = ab + AF_VH * 2, uVl = ab + AF_VL * 2;

    const int bh  = blockIdx.x;
    const int tid = threadIdx.x;
    const int lane = tid & 31;
    const int wid  = tid >> 5;
    const int grp  = lane >> 2;
    const int tig  = lane & 3;

    // ldmatrix per-lane constants
    const int rowA  = lane & 15;
    const uint32_t kselA = (uint32_t)((lane >> 4) * 16);
    const int rowB  = (lane & 7) + ((lane >> 4) << 3);
    const uint32_t kselB = (uint32_t)(((lane >> 3) & 1) * 16);

    const float4* Qg = (const float4*)(g_Q + (size_t)bh * TT * DD);
    const float4* Kg = (const float4*)(g_K + (size_t)bh * TT * DD);
    const float4* Vg = (const float4*)(g_V + (size_t)bh * TT * DD);
    #pragma unroll
    for (int j = 0; j < 16; ++j) {
        int i4 = tid + j * 256;
        int row = i4 >> 4, c4 = (i4 & 15) * 4;
        float4 qv = Qg[i4];
        uint32_t h0, l0, h1, l1;
        split_pair(qv.x, qv.y, h0, l0);
        split_pair(qv.z, qv.w, h1, l1);
        *(uint32_t*)(Qh + row * QSTR + c4)     = h0;
        *(uint32_t*)(Qh + row * QSTR + c4 + 2) = h1;
        *(uint32_t*)(Ql + row * QSTR + c4)     = l0;
        *(uint32_t*)(Ql + row * QSTR + c4 + 2) = l1;
        float4 kv = Kg[i4];
        split_pair(kv.x, kv.y, h0, l0);
        split_pair(kv.z, kv.w, h1, l1);
        *(uint32_t*)(Kh + row * QSTR + c4)     = h0;
        *(uint32_t*)(Kh + row * QSTR + c4 + 2) = h1;
        *(uint32_t*)(Kl + row * QSTR + c4)     = l0;
        *(uint32_t*)(Kl + row * QSTR + c4 + 2) = l1;
    }
    #pragma unroll
    for (int j = 0; j < 16; ++j) {
        int i4 = tid + j * 256;
        int d4 = i4 >> 8, s = i4 & 255;
        float4 vv = Vg[s * 16 + d4];
        float e[4] = {vv.x, vv.y, vv.z, vv.w};
        #pragma unroll
        for (int q = 0; q < 4; ++q) {
            int d = d4 * 4 + q;
            __nv_bfloat16 hb = __float2bfloat16(e[q]);
            Vh[d * VSTR + s] = hb;
            Vl[d * VSTR + s] = __float2bfloat16(e[q] - __bfloat162float(hb));
        }
    }
    __syncthreads();

    const float scale = 0.125f;
    const int b  = bh / HH, h = bh % HH;
    const int rbase = b * TT;

    #pragma unroll
    for (int mi = 0; mi < 2; ++mi) {
        const int tile = (mi == 0) ? wid : 15 - wid;
        const int m_lo = tile * 16;
        const int nkb  = (m_lo >> 6) + 1;
        const int r0 = m_lo + grp, r1 = r0 + 8;

        float o[8][4];
        #pragma unroll
        for (int ni = 0; ni < 8; ++ni)
            #pragma unroll
            for (int q = 0; q < 4; ++q) o[ni][q] = 0.0f;
        float lsum0 = 0.0f, lsum1 = 0.0f;

        for (int kb = 0; kb < nkb; ++kb) {
            float s[8][4];
            #pragma unroll
            for (int ni = 0; ni < 8; ++ni)
                #pragma unroll
                for (int q = 0; q < 4; ++q) s[ni][q] = 0.0f;

            // ---- S = Q Kb^T (ldmatrix frags) --------------------------------
            #pragma unroll
            for (int ks = 0; ks < 4; ++ks) {
                const uint32_t kofs = (uint32_t)(ks * 32);
                uint32_t aH[4], aL[4];
                {
                    uint32_t qa = (uint32_t)((m_lo + rowA) * 144) + kofs + kselA;
                    ldsm4(aH[0], aH[1], aH[2], aH[3], uQh + qa);
                    ldsm4(aL[0], aL[1], aL[2], aL[3], uQl + qa);
                }
                uint32_t bH[4][4], bL[4][4];
                #pragma unroll
                for (int nb = 0; nb < 4; ++nb) {
                    uint32_t ka = (uint32_t)((kb * 64 + nb * 16 + rowB) * 144) + kofs + kselB;
                    ldsm4(bH[nb][0], bH[nb][1], bH[nb][2], bH[nb][3], uKh + ka);
                    ldsm4(bL[nb][0], bL[nb][1], bL[nb][2], bL[nb][3], uKl + ka);
                }
                #pragma unroll
                for (int ni = 0; ni < 8; ++ni) {
                    uint32_t b0h = bH[ni >> 1][(ni & 1) * 2], b1h = bH[ni >> 1][(ni & 1) * 2 + 1];
                    uint32_t b0l = bL[ni >> 1][(ni & 1) * 2], b1l = bL[ni >> 1][(ni & 1) * 2 + 1];
                    mma16816(s[ni], aH, b0h, b1h);
                    mma16816(s[ni], aH, b0l, b1l);
                    mma16816(s[ni], aL, b0h, b1h);
                }
            }

            // ---- softmax weights (no-max; causal mask) ----------------------
            #pragma unroll
            for (int ni = 0; ni < 8; ++ni) {
                const int c0 = kb * 64 + ni * 8 + 2 * tig, c1 = c0 + 1;
                float e0 = (c0 <= r0) ? __expf(s[ni][0] * scale) : 0.0f;
                float e1 = (c1 <= r0) ? __expf(s[ni][1] * scale) : 0.0f;
                float e2 = (c0 <= r1) ? __expf(s[ni][2] * scale) : 0.0f;
                float e3 = (c1 <= r1) ? __expf(s[ni][3] * scale) : 0.0f;
                lsum0 += e0 + e1;
                lsum1 += e2 + e3;
                s[ni][0] = e0; s[ni][1] = e1; s[ni][2] = e2; s[ni][3] = e3;
            }

            // ---- O += P Vb (P frags from S; V frags via ldmatrix) -----------
            #pragma unroll
            for (int ksv = 0; ksv < 4; ++ksv) {
                uint32_t paH[4], paL[4];
                split_pair(s[2*ksv][0],   s[2*ksv][1],   paH[0], paL[0]);
                split_pair(s[2*ksv][2],   s[2*ksv][3],   paH[1], paL[1]);
                split_pair(s[2*ksv+1][0], s[2*ksv+1][1], paH[2], paL[2]);
                split_pair(s[2*ksv+1][2], s[2*ksv+1][3], paH[3], paL[3]);
                const uint32_t colb = (uint32_t)((kb * 64 + ksv * 16) * 2) + kselB;
                uint32_t vbH[4][4], vbL[4][4];
                #pragma unroll
                for (int nb = 0; nb < 4; ++nb) {
                    uint32_t va = (uint32_t)((nb * 16 + rowB) * (VSTR * 2)) + colb;
                    ldsm4(vbH[nb][0], vbH[nb][1], vbH[nb][2], vbH[nb][3], uVh + va);
                    ldsm4(vbL[nb][0], vbL[nb][1], vbL[nb][2], vbL[nb][3], uVl + va);
                }
                #pragma unroll
                for (int ni = 0; ni < 8; ++ni) {
                    uint32_t b0h = vbH[ni >> 1][(ni & 1) * 2], b1h = vbH[ni >> 1][(ni & 1) * 2 + 1];
                    uint32_t b0l = vbL[ni >> 1][(ni & 1) * 2], b1l = vbL[ni >> 1][(ni & 1) * 2 + 1];
                    mma16816(o[ni], paH, b0h, b1h);
                    mma16816(o[ni], paL, b0h, b1h);
                    mma16816(o[ni], paH, b0l, b1l);
                }
            }
        }

        lsum0 += __shfl_xor_sync(0xffffffffu, lsum0, 1);
        lsum0 += __shfl_xor_sync(0xffffffffu, lsum0, 2);
        lsum1 += __shfl_xor_sync(0xffffffffu, lsum1, 1);
        lsum1 += __shfl_xor_sync(0xffffffffu, lsum1, 2);
        const float inv0 = 1.0f / lsum0, inv1 = 1.0f / lsum1;

        #pragma unroll
        for (int ni = 0; ni < 8; ++ni) {
            const int col = h * 64 + ni * 8 + 2 * tig;
            uint32_t hv, lv;
            split_pair(o[ni][0] * inv0, o[ni][1] * inv0, hv, lv);
            *(uint32_t*)(g_Ah + (size_t)(rbase + r0) * CC + col) = hv;
            *(uint32_t*)(g_Al + (size_t)(rbase + r0) * CC + col) = lv;
            split_pair(o[ni][2] * inv1, o[ni][3] * inv1, hv, lv);
            *(uint32_t*)(g_Ah + (size_t)(rbase + r1) * CC + col) = hv;
            *(uint32_t*)(g_Al + (size_t)(rbase + r1) * CC + col) = lv;
        }
    }
}

// ---------------------------------------------------------------------------
extern "C" void kernel_launch(void* const* d_in, const int* in_sizes, int n_in,
                              void* d_out, int out_size)
{
    const float* x  = (const float*)d_in[0];
    const float* Wq = (const float*)d_in[1];
    const float* Wk = (const float*)d_in[2];
    const float* Wv = (const float*)d_in[3];
    const float* Wp = (const float*)d_in[4];
    const float* bp = (const float*)d_in[5];
    float* out = (float*)d_out;

    const int HMMA_SMEM = 2 * HS_TOT * (int)sizeof(__nv_bfloat16);  // 110592 B
    const int ATTN_SMEM = AF_TOT * (int)sizeof(__nv_bfloat16);      // 215040 B
    cudaFuncSetAttribute(hmma_gemm, cudaFuncAttributeMaxDynamicSharedMemorySize, HMMA_SMEM);
    cudaFuncSetAttribute(attn_flash, cudaFuncAttributeMaxDynamicSharedMemorySize, ATTN_SMEM);

    conv_x<<<BT*CC/256, 256>>>(x);
    conv_w<<<3*CC*CC/256, 256>>>(Wq, Wk, Wv);
    conv_wp<<<CC*CC/256, 256>>>(Wp);
    hmma_gemm<<<dim3(BT/128, 18), 256, HMMA_SMEM>>>(0, nullptr, nullptr);
    attn_flash<<<BB*HH, 256, ATTN_SMEM>>>();
    hmma_gemm<<<dim3(BT/128, 6), 256, HMMA_SMEM>>>(1, bp, out);
}